// round 7
// baseline (speedup 1.0000x reference)
#include <cuda_runtime.h>
#include <cuda_bf16.h>
#include <cstdint>

static const int MAXN = 50000;

__device__ float g_Q [MAXN * 128];
__device__ float g_K [MAXN * 128];
__device__ float g_V [MAXN * 128];
__device__ float g_wV[MAXN * 128];
__device__ float g_z [MAXN * 8];

// ================= helpers =================
__device__ __forceinline__ uint32_t smem_u32(const void* p) {
    uint32_t a;
    asm("{ .reg .u64 t; cvta.to.shared.u64 t, %1; cvt.u32.u64 %0, t; }" : "=r"(a) : "l"(p));
    return a;
}
__device__ __forceinline__ void ldsm4(uint32_t& r0, uint32_t& r1, uint32_t& r2, uint32_t& r3,
                                      uint32_t addr) {
    asm volatile("ldmatrix.sync.aligned.m8n8.x4.shared.b16 {%0,%1,%2,%3}, [%4];"
                 : "=r"(r0), "=r"(r1), "=r"(r2), "=r"(r3) : "r"(addr));
}
__device__ __forceinline__ void mma16816(float* c,
                                         uint32_t a0, uint32_t a1, uint32_t a2, uint32_t a3,
                                         uint32_t b0, uint32_t b1) {
    asm volatile("mma.sync.aligned.m16n8k16.row.col.f32.bf16.bf16.f32 "
                 "{%0,%1,%2,%3}, {%4,%5,%6,%7}, {%8,%9}, {%0,%1,%2,%3};"
                 : "+f"(c[0]), "+f"(c[1]), "+f"(c[2]), "+f"(c[3])
                 : "r"(a0), "r"(a1), "r"(a2), "r"(a3), "r"(b0), "r"(b1));
}
__device__ __forceinline__ void red_v4(float* p, float a, float b, float c, float d) {
    asm volatile("red.global.add.v4.f32 [%0], {%1, %2, %3, %4};"
                 :: "l"(p), "f"(a), "f"(b), "f"(c), "f"(d) : "memory");
}
__device__ __forceinline__ void red_f32(float* p, float a) {
    asm volatile("red.global.add.f32 [%0], %1;" :: "l"(p), "f"(a) : "memory");
}

// ---- smem layout: padded 272B rows (16B pad -> ldmatrix conflict-free) ----
#define SK    272
#define S_AH  0
#define S_AL  34816
#define S_WH  69632
#define S_WL  104448
#define S_TOT 139264
// fp32 proj scratch overlays the (dead-after-mainloop) A region: 128*512 = 64KB <= 69632

#define GT 256

__device__ __forceinline__ void split_bf16(float x, __nv_bfloat16& h, __nv_bfloat16& l) {
    h = __float2bfloat16(x);
    l = __float2bfloat16(x - __bfloat162float(h));
}

// ---------- shared GEMM building blocks ----------
struct Frag { uint32_t aH, aL, bH, bL; };

__device__ __forceinline__ void conv_W(const float* __restrict__ W, char* smem, int tid) {
    for (int i = tid; i < 4096; i += GT) {
        int k = i >> 5, n4 = (i & 31) << 2;
        float4 w = *reinterpret_cast<const float4*>(W + k * 128 + n4);
        const float* wp = &w.x;
        #pragma unroll
        for (int j = 0; j < 4; j++) {
            __nv_bfloat16 h, l;
            split_bf16(wp[j], h, l);
            int off = (n4 + j) * SK + k * 2;
            *reinterpret_cast<__nv_bfloat16*>(smem + S_WH + off) = h;
            *reinterpret_cast<__nv_bfloat16*>(smem + S_WL + off) = l;
        }
    }
}

__device__ __forceinline__ void stage_A(const float* __restrict__ A, long rows, long t,
                                        float4* rg, int tid) {
    #pragma unroll
    for (int i = 0; i < 16; i++) {
        int idx = i * GT + tid;
        int m = idx >> 5, c4 = (idx & 31) << 2;
        long row = t * 128 + m;
        rg[i] = (row < rows) ? *reinterpret_cast<const float4*>(A + row * 128 + c4)
                             : make_float4(0.f, 0.f, 0.f, 0.f);
    }
}

__device__ __forceinline__ void store_A(const float4* rg, char* smem, int tid) {
    #pragma unroll
    for (int i = 0; i < 16; i++) {
        int idx = i * GT + tid;
        int m = idx >> 5, c4 = (idx & 31) << 2;
        const float* ap = &rg[i].x;
        __nv_bfloat16 h0, l0, h1, l1, h2, l2, h3, l3;
        split_bf16(ap[0], h0, l0); split_bf16(ap[1], h1, l1);
        split_bf16(ap[2], h2, l2); split_bf16(ap[3], h3, l3);
        __nv_bfloat162 hp0 = __halves2bfloat162(h0, h1), hp1 = __halves2bfloat162(h2, h3);
        __nv_bfloat162 lp0 = __halves2bfloat162(l0, l1), lp1 = __halves2bfloat162(l2, l3);
        int off = m * SK + c4 * 2;
        *reinterpret_cast<uint2*>(smem + S_AH + off) =
            make_uint2(*reinterpret_cast<uint32_t*>(&hp0), *reinterpret_cast<uint32_t*>(&hp1));
        *reinterpret_cast<uint2*>(smem + S_AL + off) =
            make_uint2(*reinterpret_cast<uint32_t*>(&lp0), *reinterpret_cast<uint32_t*>(&lp1));
    }
}

__device__ __forceinline__ void mma_mainloop(uint32_t aH, uint32_t aL, uint32_t bH, uint32_t bL,
                                             float* acc) {
    #pragma unroll
    for (int i = 0; i < 64; i++) acc[i] = 0.f;
    #pragma unroll 2
    for (int ks = 0; ks < 8; ks++) {
        const uint32_t ko = ks * 32;
        uint32_t ah0, ah1, ah2, ah3, al0, al1, al2, al3;
        ldsm4(ah0, ah1, ah2, ah3, aH + ko);
        ldsm4(al0, al1, al2, al3, aL + ko);
        #pragma unroll
        for (int np = 0; np < 4; np++) {
            const uint32_t boA = (np * 2 + 0) * (16 * SK) + ko;
            const uint32_t boB = (np * 2 + 1) * (16 * SK) + ko;
            uint32_t xh0, xh1, xh2, xh3, xl0, xl1, xl2, xl3;
            uint32_t yh0, yh1, yh2, yh3, yl0, yl1, yl2, yl3;
            ldsm4(xh0, xh1, xh2, xh3, bH + boA);
            ldsm4(xl0, xl1, xl2, xl3, bL + boA);
            ldsm4(yh0, yh1, yh2, yh3, bH + boB);
            ldsm4(yl0, yl1, yl2, yl3, bL + boB);
            float* cA0 = acc + np * 16;
            float* cA1 = acc + np * 16 + 4;
            float* cB0 = acc + np * 16 + 8;
            float* cB1 = acc + np * 16 + 12;
            mma16816(cA0, ah0, ah1, ah2, ah3, xh0, xh1);
            mma16816(cA1, ah0, ah1, ah2, ah3, xh2, xh3);
            mma16816(cB0, ah0, ah1, ah2, ah3, yh0, yh1);
            mma16816(cB1, ah0, ah1, ah2, ah3, yh2, yh3);
            mma16816(cA0, ah0, ah1, ah2, ah3, xl0, xl1);
            mma16816(cA1, ah0, ah1, ah2, ah3, xl2, xl3);
            mma16816(cB0, ah0, ah1, ah2, ah3, yl0, yl1);
            mma16816(cB1, ah0, ah1, ah2, ah3, yl2, yl3);
            mma16816(cA0, al0, al1, al2, al3, xh0, xh1);
            mma16816(cA1, al0, al1, al2, al3, xh2, xh3);
            mma16816(cB0, al0, al1, al2, al3, yh0, yh1);
            mma16816(cB1, al0, al1, al2, al3, yh2, yh3);
        }
    }
}

// ================ kernel 1: node QKV GEMM (store C to global) ================
__global__ void __launch_bounds__(GT, 1)
hmma_gemm_kernel(const float* __restrict__ A, const float* __restrict__ W,
                 const float* __restrict__ bias, float* __restrict__ C,
                 long rows, long ntiles) {
    extern __shared__ __align__(16) char smem[];
    const uint32_t sb = smem_u32(smem);
    const int tid = threadIdx.x, wid = tid >> 5, lane = tid & 31;

    conv_W(W, smem, tid);

    const int q = lane >> 3, r = lane & 7;
    const uint32_t a_row = (uint32_t)(wid * 16 + r + (q & 1) * 8);
    const uint32_t a_kb  = (uint32_t)((q >> 1) * 16);
    const uint32_t aH = sb + S_AH + a_row * SK + a_kb;
    const uint32_t aL = sb + S_AL + a_row * SK + a_kb;
    const uint32_t b_off = (uint32_t)((r + (q >> 1) * 8) * SK + (q & 1) * 16);
    const uint32_t bH = sb + S_WH + b_off;
    const uint32_t bL = sb + S_WL + b_off;

    float4 rg[16];
    long t = blockIdx.x;
    stage_A(A, rows, t, rg, tid);
    __syncthreads();

    for (; t < ntiles; ) {
        store_A(rg, smem, tid);
        __syncthreads();

        long tn = t + gridDim.x;
        if (tn < ntiles) stage_A(A, rows, tn, rg, tid);

        float acc[64];
        mma_mainloop(aH, aL, bH, bL, acc);

        long gr0 = t * 128 + wid * 16 + (lane >> 2);
        long gr1 = gr0 + 8;
        #pragma unroll
        for (int i8 = 0; i8 < 16; i8++) {
            int col = i8 * 8 + (lane & 3) * 2;
            float2 bb = *reinterpret_cast<const float2*>(bias + col);
            const float* cp = acc + i8 * 4;
            if (gr0 < rows)
                *reinterpret_cast<float2*>(C + gr0 * 128 + col) = make_float2(cp[0] + bb.x, cp[1] + bb.y);
            if (gr1 < rows)
                *reinterpret_cast<float2*>(C + gr1 * 128 + col) = make_float2(cp[2] + bb.x, cp[3] + bb.y);
        }
        __syncthreads();
        t = tn;
    }
}

// ================ kernel 2: FUSED edge GEMM + attention epilogue ================
__global__ void __launch_bounds__(GT, 1)
edge_fused_kernel(const float* __restrict__ A, const float* __restrict__ W,
                  const float* __restrict__ bias,
                  const float* __restrict__ envelope,
                  const int* __restrict__ src, const int* __restrict__ dst,
                  float* __restrict__ eout,
                  long rows, long ntiles) {
    extern __shared__ __align__(16) char smem[];
    const uint32_t sb = smem_u32(smem);
    const int tid = threadIdx.x, wid = tid >> 5, lane = tid & 31;

    conv_W(W, smem, tid);

    const int q = lane >> 3, r = lane & 7;
    const uint32_t a_row = (uint32_t)(wid * 16 + r + (q & 1) * 8);
    const uint32_t a_kb  = (uint32_t)((q >> 1) * 16);
    const uint32_t aH = sb + S_AH + a_row * SK + a_kb;
    const uint32_t aL = sb + S_AL + a_row * SK + a_kb;
    const uint32_t b_off = (uint32_t)((r + (q >> 1) * 8) * SK + (q & 1) * 16);
    const uint32_t bH = sb + S_WH + b_off;
    const uint32_t bL = sb + S_WL + b_off;

    float* proj = reinterpret_cast<float*>(smem);   // overlays A region after mainloop

    float4 rg[16];
    long t = blockIdx.x;
    stage_A(A, rows, t, rg, tid);
    __syncthreads();

    for (; t < ntiles; ) {
        store_A(rg, smem, tid);
        __syncthreads();

        long tn = t + gridDim.x;
        if (tn < ntiles) stage_A(A, rows, tn, rg, tid);   // LDGs in flight through mma+epilogue

        float acc[64];
        mma_mainloop(aH, aL, bH, bL, acc);
        __syncthreads();   // everyone done reading A smem

        // ---- dump proj (+bias) into smem (fp32, row-major 128 floats/row) ----
        {
            int r0 = wid * 16 + (lane >> 2);
            #pragma unroll
            for (int i8 = 0; i8 < 16; i8++) {
                int col = i8 * 8 + (lane & 3) * 2;
                float2 bb = *reinterpret_cast<const float2*>(bias + col);
                const float* cp = acc + i8 * 4;
                *reinterpret_cast<float2*>(proj + r0 * 128 + col) =
                    make_float2(cp[0] + bb.x, cp[1] + bb.y);
                *reinterpret_cast<float2*>(proj + (r0 + 8) * 128 + col) =
                    make_float2(cp[2] + bb.x, cp[3] + bb.y);
            }
        }
        __syncthreads();

        // ---- warp-per-edge epilogue: 16 edges per warp, proj from smem ----
        {
            const long ebase = t * 128 + wid * 16;
            const int c = lane << 2;
            #pragma unroll 4
            for (int j = 0; j < 16; j++) {
                long ed = ebase + j;
                if (ed >= rows) break;
                int ml = wid * 16 + j;
                int si = __ldg(src + ed);
                int di = __ldg(dst + ed);
                float env = __ldg(envelope + ed);

                float4 pv = *reinterpret_cast<const float4*>(proj + ml * 128 + c);
                float4 kv = *reinterpret_cast<const float4*>(g_K + (long)si * 128 + c);
                float4 qv = *reinterpret_cast<const float4*>(g_Q + (long)di * 128 + c);
                float4 vv = *reinterpret_cast<const float4*>(g_V + (long)si * 128 + c);

                float4 sc;
                sc.x = kv.x * qv.x * 0.25f * pv.x;
                sc.y = kv.y * qv.y * 0.25f * pv.y;
                sc.z = kv.z * qv.z * 0.25f * pv.z;
                sc.w = kv.w * qv.w * 0.25f * pv.w;

                float part = (sc.x + sc.y) + (sc.z + sc.w);
                part += __shfl_xor_sync(0xFFFFFFFFu, part, 1);
                part += __shfl_xor_sync(0xFFFFFFFFu, part, 2);
                float s = __expf(fminf(fmaxf(part, -5.f), 5.f));
                float es = env * s;

                *reinterpret_cast<float4*>(eout + ed * 128 + c) = sc;

                float* w = g_wV + (long)di * 128 + c;
                red_v4(w, vv.x * es, vv.y * es, vv.z * es, vv.w * es);
                if ((lane & 3) == 0) red_f32(g_z + (long)di * 8 + (lane >> 2), s);
            }
        }
        __syncthreads();
        t = tn;
    }
}

// ================= small kernels =================
__global__ void zero_kernel(int N) {
    int i = blockIdx.x * blockDim.x + threadIdx.x;
    if (i < N * 128) g_wV[i] = 0.f;
    if (i < N * 8)   g_z[i]  = 0.f;
}

__global__ void norm_kernel(float* __restrict__ vout, int N) {
    int i = blockIdx.x * blockDim.x + threadIdx.x;
    if (i < N * 128) {
        int n = i >> 7;
        int c = i & 127;
        vout[i] = g_wV[i] / (g_z[n * 8 + (c >> 4)] + 1e-6f);
    }
}

extern "C" void kernel_launch(void* const* d_in, const int* in_sizes, int n_in,
                              void* d_out, int out_size) {
    const float* v        = (const float*)d_in[0];
    const float* e        = (const float*)d_in[1];
    const float* envelope = (const float*)d_in[2];
    const float* Wq       = (const float*)d_in[3];
    const float* bq       = (const float*)d_in[4];
    const float* Wk       = (const float*)d_in[5];
    const float* bk       = (const float*)d_in[6];
    const float* Wv       = (const float*)d_in[7];
    const float* bv       = (const float*)d_in[8];
    const float* We       = (const float*)d_in[9];
    const float* be       = (const float*)d_in[10];
    const int*   src      = (const int*)d_in[11];
    const int*   dst      = (const int*)d_in[12];

    int N = in_sizes[0] / 128;
    int E = in_sizes[11];

    float* out  = (float*)d_out;
    float* vout = out;
    float* eout = out + (long)N * 128;

    float *gq, *gk, *gv;
    cudaGetSymbolAddress((void**)&gq, g_Q);
    cudaGetSymbolAddress((void**)&gk, g_K);
    cudaGetSymbolAddress((void**)&gv, g_V);
    cudaFuncSetAttribute(hmma_gemm_kernel,  cudaFuncAttributeMaxDynamicSharedMemorySize, S_TOT);
    cudaFuncSetAttribute(edge_fused_kernel, cudaFuncAttributeMaxDynamicSharedMemorySize, S_TOT);

    long tilesN = (N + 127) / 128;
    long tilesE = (E + 127) / 128;
    int gridN = (int)((tilesN < 148) ? tilesN : 148);
    int gridE = (int)((tilesE < 148) ? tilesE : 148);

    zero_kernel<<<(N * 128 + 255) / 256, 256>>>(N);
    hmma_gemm_kernel<<<gridN, GT, S_TOT>>>(v, Wq, bq, gq, N, tilesN);
    hmma_gemm_kernel<<<gridN, GT, S_TOT>>>(v, Wk, bk, gk, N, tilesN);
    hmma_gemm_kernel<<<gridN, GT, S_TOT>>>(v, Wv, bv, gv, N, tilesN);
    edge_fused_kernel<<<gridE, GT, S_TOT>>>(e, We, be, envelope, src, dst, eout, E, tilesE);
    norm_kernel<<<(N * 128 + 255) / 256, 256>>>(vout, N);
}

// round 10
// speedup vs baseline: 1.4691x; 1.4691x over previous
#include <cuda_runtime.h>
#include <cuda_bf16.h>
#include <cstdint>

static const int MAXN = 50000;

__device__ float g_Q [MAXN * 128];
__device__ float g_K [MAXN * 128];
__device__ float g_V [MAXN * 128];
__device__ float g_wV[MAXN * 128];
__device__ float g_z [MAXN * 8];

// ================= helpers =================
__device__ __forceinline__ uint32_t smem_u32(const void* p) {
    uint32_t a;
    asm("{ .reg .u64 t; cvta.to.shared.u64 t, %1; cvt.u32.u64 %0, t; }" : "=r"(a) : "l"(p));
    return a;
}
__device__ __forceinline__ void ldsm4(uint32_t& r0, uint32_t& r1, uint32_t& r2, uint32_t& r3,
                                      uint32_t addr) {
    asm volatile("ldmatrix.sync.aligned.m8n8.x4.shared.b16 {%0,%1,%2,%3}, [%4];"
                 : "=r"(r0), "=r"(r1), "=r"(r2), "=r"(r3) : "r"(addr));
}
__device__ __forceinline__ void mma16816(float* c,
                                         uint32_t a0, uint32_t a1, uint32_t a2, uint32_t a3,
                                         uint32_t b0, uint32_t b1) {
    asm volatile("mma.sync.aligned.m16n8k16.row.col.f32.bf16.bf16.f32 "
                 "{%0,%1,%2,%3}, {%4,%5,%6,%7}, {%8,%9}, {%0,%1,%2,%3};"
                 : "+f"(c[0]), "+f"(c[1]), "+f"(c[2]), "+f"(c[3])
                 : "r"(a0), "r"(a1), "r"(a2), "r"(a3), "r"(b0), "r"(b1));
}
__device__ __forceinline__ void red_v4(float* p, float a, float b, float c, float d) {
    asm volatile("red.global.add.v4.f32 [%0], {%1, %2, %3, %4};"
                 :: "l"(p), "f"(a), "f"(b), "f"(c), "f"(d) : "memory");
}
__device__ __forceinline__ void red_f32(float* p, float a) {
    asm volatile("red.global.add.f32 [%0], %1;" :: "l"(p), "f"(a) : "memory");
}

// ---- smem layout: padded 272B rows (16B pad -> ldmatrix conflict-free) ----
#define SK    272
#define S_AH  0
#define S_AL  34816
#define S_WH  69632
#define S_WL  104448
#define S_TOT 139264

#define GT 256

__device__ __forceinline__ void split_bf16(float x, __nv_bfloat16& h, __nv_bfloat16& l) {
    h = __float2bfloat16(x);
    l = __float2bfloat16(x - __bfloat162float(h));
}

__device__ __forceinline__ void conv_W(const float* __restrict__ W, char* smem, int tid) {
    for (int i = tid; i < 4096; i += GT) {
        int k = i >> 5, n4 = (i & 31) << 2;
        float4 w = *reinterpret_cast<const float4*>(W + k * 128 + n4);
        const float* wp = &w.x;
        #pragma unroll
        for (int j = 0; j < 4; j++) {
            __nv_bfloat16 h, l;
            split_bf16(wp[j], h, l);
            int off = (n4 + j) * SK + k * 2;
            *reinterpret_cast<__nv_bfloat16*>(smem + S_WH + off) = h;
            *reinterpret_cast<__nv_bfloat16*>(smem + S_WL + off) = l;
        }
    }
}

__device__ __forceinline__ void stage_A(const float* __restrict__ A, long rows, long t,
                                        float4* rg, int tid) {
    #pragma unroll
    for (int i = 0; i < 16; i++) {
        int idx = i * GT + tid;
        int m = idx >> 5, c4 = (idx & 31) << 2;
        long row = t * 128 + m;
        rg[i] = (row < rows) ? *reinterpret_cast<const float4*>(A + row * 128 + c4)
                             : make_float4(0.f, 0.f, 0.f, 0.f);
    }
}

__device__ __forceinline__ void store_A(const float4* rg, char* smem, int tid) {
    #pragma unroll
    for (int i = 0; i < 16; i++) {
        int idx = i * GT + tid;
        int m = idx >> 5, c4 = (idx & 31) << 2;
        const float* ap = &rg[i].x;
        __nv_bfloat16 h0, l0, h1, l1, h2, l2, h3, l3;
        split_bf16(ap[0], h0, l0); split_bf16(ap[1], h1, l1);
        split_bf16(ap[2], h2, l2); split_bf16(ap[3], h3, l3);
        __nv_bfloat162 hp0 = __halves2bfloat162(h0, h1), hp1 = __halves2bfloat162(h2, h3);
        __nv_bfloat162 lp0 = __halves2bfloat162(l0, l1), lp1 = __halves2bfloat162(l2, l3);
        int off = m * SK + c4 * 2;
        *reinterpret_cast<uint2*>(smem + S_AH + off) =
            make_uint2(*reinterpret_cast<uint32_t*>(&hp0), *reinterpret_cast<uint32_t*>(&hp1));
        *reinterpret_cast<uint2*>(smem + S_AL + off) =
            make_uint2(*reinterpret_cast<uint32_t*>(&lp0), *reinterpret_cast<uint32_t*>(&lp1));
    }
}

// 2-D warp tiling: warp = (mw 0..3, nw 0..1); warp tile M32 x N64.
// acc layout: [nb*16 + mb*8 + n8*4 + {0..3}]
__device__ __forceinline__ void mma_mainloop(uint32_t aH0, uint32_t aH1,
                                             uint32_t aL0, uint32_t aL1,
                                             uint32_t bHb, uint32_t bLb, float* acc) {
    #pragma unroll
    for (int i = 0; i < 64; i++) acc[i] = 0.f;
    #pragma unroll
    for (int ks = 0; ks < 8; ks++) {
        const uint32_t ko = ks * 32;
        uint32_t h00, h01, h02, h03, h10, h11, h12, h13;
        uint32_t l00, l01, l02, l03, l10, l11, l12, l13;
        ldsm4(h00, h01, h02, h03, aH0 + ko);
        ldsm4(h10, h11, h12, h13, aH1 + ko);
        ldsm4(l00, l01, l02, l03, aL0 + ko);
        ldsm4(l10, l11, l12, l13, aL1 + ko);
        #pragma unroll
        for (int nb = 0; nb < 4; nb++) {
            const uint32_t off = (uint32_t)nb * (16 * SK) + ko;
            uint32_t xh0, xh1, xh2, xh3, xl0, xl1, xl2, xl3;
            ldsm4(xh0, xh1, xh2, xh3, bHb + off);
            ldsm4(xl0, xl1, xl2, xl3, bLb + off);
            float* c00 = acc + nb * 16;
            float* c01 = acc + nb * 16 + 4;
            float* c10 = acc + nb * 16 + 8;
            float* c11 = acc + nb * 16 + 12;
            // hi*hi
            mma16816(c00, h00, h01, h02, h03, xh0, xh1);
            mma16816(c01, h00, h01, h02, h03, xh2, xh3);
            mma16816(c10, h10, h11, h12, h13, xh0, xh1);
            mma16816(c11, h10, h11, h12, h13, xh2, xh3);
            // hi*lo
            mma16816(c00, h00, h01, h02, h03, xl0, xl1);
            mma16816(c01, h00, h01, h02, h03, xl2, xl3);
            mma16816(c10, h10, h11, h12, h13, xl0, xl1);
            mma16816(c11, h10, h11, h12, h13, xl2, xl3);
            // lo*hi
            mma16816(c00, l00, l01, l02, l03, xh0, xh1);
            mma16816(c01, l00, l01, l02, l03, xh2, xh3);
            mma16816(c10, l10, l11, l12, l13, xh0, xh1);
            mma16816(c11, l10, l11, l12, l13, xh2, xh3);
        }
    }
}

// ================ GEMM: C[rows x 128] = A @ W + bias ================
__global__ void __launch_bounds__(GT, 1)
hmma_gemm_kernel(const float* __restrict__ A, const float* __restrict__ W,
                 const float* __restrict__ bias, float* __restrict__ C,
                 long rows, long ntiles) {
    extern __shared__ __align__(16) char smem[];
    const uint32_t sb = smem_u32(smem);
    const int tid = threadIdx.x, wid = tid >> 5, lane = tid & 31;
    const int mw = wid & 3, nw = wid >> 2;

    conv_W(W, smem, tid);

    const int q = lane >> 3, r = lane & 7;
    const uint32_t aRow = (uint32_t)(mw * 32 + r + (q & 1) * 8);
    const uint32_t a_kb = (uint32_t)((q >> 1) * 16);
    const uint32_t aH0 = sb + S_AH + aRow * SK + a_kb;
    const uint32_t aH1 = aH0 + 16 * SK;
    const uint32_t aL0 = sb + S_AL + aRow * SK + a_kb;
    const uint32_t aL1 = aL0 + 16 * SK;
    const uint32_t bRow = (uint32_t)(nw * 64 + r + (q >> 1) * 8);
    const uint32_t b_kb = (uint32_t)((q & 1) * 16);
    const uint32_t bHb = sb + S_WH + bRow * SK + b_kb;
    const uint32_t bLb = sb + S_WL + bRow * SK + b_kb;

    float4 rg[16];
    long t = blockIdx.x;
    stage_A(A, rows, t, rg, tid);
    __syncthreads();

    for (; t < ntiles; ) {
        store_A(rg, smem, tid);
        __syncthreads();

        long tn = t + gridDim.x;
        if (tn < ntiles) stage_A(A, rows, tn, rg, tid);

        float acc[64];
        mma_mainloop(aH0, aH1, aL0, aL1, bHb, bLb, acc);

        // epilogue: add bias, store C
        const long mbase = t * 128 + mw * 32;
        #pragma unroll
        for (int nb = 0; nb < 4; nb++) {
            #pragma unroll
            for (int n8 = 0; n8 < 2; n8++) {
                int col = nw * 64 + nb * 16 + n8 * 8 + (lane & 3) * 2;
                float2 bb = *reinterpret_cast<const float2*>(bias + col);
                #pragma unroll
                for (int mb = 0; mb < 2; mb++) {
                    const float* cp = acc + nb * 16 + mb * 8 + n8 * 4;
                    long r0 = mbase + mb * 16 + (lane >> 2);
                    long r1 = r0 + 8;
                    if (r0 < rows)
                        *reinterpret_cast<float2*>(C + r0 * 128 + col) =
                            make_float2(cp[0] + bb.x, cp[1] + bb.y);
                    if (r1 < rows)
                        *reinterpret_cast<float2*>(C + r1 * 128 + col) =
                            make_float2(cp[2] + bb.x, cp[3] + bb.y);
                }
            }
        }
        __syncthreads();
        t = tn;
    }
}

// ================= non-GEMM kernels =================
__global__ void zero_kernel(int N) {
    int i = blockIdx.x * blockDim.x + threadIdx.x;
    if (i < N * 128) g_wV[i] = 0.f;
    if (i < N * 8)   g_z[i]  = 0.f;
}

__global__ void __launch_bounds__(256)
edge_epilogue_kernel(const float* __restrict__ envelope,
                     const int* __restrict__ src, const int* __restrict__ dst,
                     float* __restrict__ eout, int E) {
    int warp = (blockIdx.x * blockDim.x + threadIdx.x) >> 5;
    int lane = threadIdx.x & 31;
    if (warp >= E) return;

    int si = __ldg(src + warp);
    int di = __ldg(dst + warp);
    float env = __ldg(envelope + warp);

    int c = lane << 2;
    const float4 kv = *reinterpret_cast<const float4*>(g_K + (long)si * 128 + c);
    const float4 qv = *reinterpret_cast<const float4*>(g_Q + (long)di * 128 + c);
    const float4 vv = *reinterpret_cast<const float4*>(g_V + (long)si * 128 + c);
    float* ep = eout + (long)warp * 128 + c;
    const float4 pv = *reinterpret_cast<const float4*>(ep);

    float4 sc;
    sc.x = kv.x * qv.x * 0.25f * pv.x;
    sc.y = kv.y * qv.y * 0.25f * pv.y;
    sc.z = kv.z * qv.z * 0.25f * pv.z;
    sc.w = kv.w * qv.w * 0.25f * pv.w;

    float part = (sc.x + sc.y) + (sc.z + sc.w);
    part += __shfl_xor_sync(0xFFFFFFFFu, part, 1);
    part += __shfl_xor_sync(0xFFFFFFFFu, part, 2);
    float s = __expf(fminf(fmaxf(part, -5.f), 5.f));
    float es = env * s;

    *reinterpret_cast<float4*>(ep) = sc;

    float* w = g_wV + (long)di * 128 + c;
    red_v4(w, vv.x * es, vv.y * es, vv.z * es, vv.w * es);
    if ((lane & 3) == 0) red_f32(g_z + (long)di * 8 + (lane >> 2), s);
}

__global__ void norm_kernel(float* __restrict__ vout, int N) {
    int i = blockIdx.x * blockDim.x + threadIdx.x;
    if (i < N * 128) {
        int n = i >> 7;
        int c = i & 127;
        vout[i] = g_wV[i] / (g_z[n * 8 + (c >> 4)] + 1e-6f);
    }
}

extern "C" void kernel_launch(void* const* d_in, const int* in_sizes, int n_in,
                              void* d_out, int out_size) {
    const float* v        = (const float*)d_in[0];
    const float* e        = (const float*)d_in[1];
    const float* envelope = (const float*)d_in[2];
    const float* Wq       = (const float*)d_in[3];
    const float* bq       = (const float*)d_in[4];
    const float* Wk       = (const float*)d_in[5];
    const float* bk       = (const float*)d_in[6];
    const float* Wv       = (const float*)d_in[7];
    const float* bv       = (const float*)d_in[8];
    const float* We       = (const float*)d_in[9];
    const float* be       = (const float*)d_in[10];
    const int*   src      = (const int*)d_in[11];
    const int*   dst      = (const int*)d_in[12];

    int N = in_sizes[0] / 128;
    int E = in_sizes[11];

    float* out  = (float*)d_out;
    float* vout = out;
    float* eout = out + (long)N * 128;

    float *gq, *gk, *gv;
    cudaGetSymbolAddress((void**)&gq, g_Q);
    cudaGetSymbolAddress((void**)&gk, g_K);
    cudaGetSymbolAddress((void**)&gv, g_V);
    cudaFuncSetAttribute(hmma_gemm_kernel, cudaFuncAttributeMaxDynamicSharedMemorySize, S_TOT);

    long tilesN = (N + 127) / 128;
    long tilesE = (E + 127) / 128;
    int gridN = (int)((tilesN < 148) ? tilesN : 148);
    int gridE = (int)((tilesE < 148) ? tilesE : 148);

    zero_kernel<<<(N * 128 + 255) / 256, 256>>>(N);
    hmma_gemm_kernel<<<gridN, GT, S_TOT>>>(v, Wq, bq, gq, N, tilesN);
    hmma_gemm_kernel<<<gridN, GT, S_TOT>>>(v, Wk, bk, gk, N, tilesN);
    hmma_gemm_kernel<<<gridN, GT, S_TOT>>>(v, Wv, bv, gv, N, tilesN);
    hmma_gemm_kernel<<<gridE, GT, S_TOT>>>(e, We, be, eout, E, tilesE);
    edge_epilogue_kernel<<<(E * 32 + 255) / 256, 256>>>(envelope, src, dst, eout, E);
    norm_kernel<<<(N * 128 + 255) / 256, 256>>>(vout, N);
}

// round 11
// speedup vs baseline: 1.4699x; 1.0005x over previous
#include <cuda_runtime.h>
#include <cuda_bf16.h>
#include <cstdint>

static const int MAXN = 50000;

__device__ float g_Q [MAXN * 128];
__device__ float g_K [MAXN * 128];
__device__ float g_V [MAXN * 128];
__device__ float g_wV[MAXN * 128];
__device__ float g_z [MAXN * 8];

// ================= helpers =================
__device__ __forceinline__ uint32_t smem_u32(const void* p) {
    uint32_t a;
    asm("{ .reg .u64 t; cvta.to.shared.u64 t, %1; cvt.u32.u64 %0, t; }" : "=r"(a) : "l"(p));
    return a;
}
__device__ __forceinline__ void ldsm4(uint32_t& r0, uint32_t& r1, uint32_t& r2, uint32_t& r3,
                                      uint32_t addr) {
    asm volatile("ldmatrix.sync.aligned.m8n8.x4.shared.b16 {%0,%1,%2,%3}, [%4];"
                 : "=r"(r0), "=r"(r1), "=r"(r2), "=r"(r3) : "r"(addr));
}
__device__ __forceinline__ void mma16816(float* c,
                                         uint32_t a0, uint32_t a1, uint32_t a2, uint32_t a3,
                                         uint32_t b0, uint32_t b1) {
    asm volatile("mma.sync.aligned.m16n8k16.row.col.f32.bf16.bf16.f32 "
                 "{%0,%1,%2,%3}, {%4,%5,%6,%7}, {%8,%9}, {%0,%1,%2,%3};"
                 : "+f"(c[0]), "+f"(c[1]), "+f"(c[2]), "+f"(c[3])
                 : "r"(a0), "r"(a1), "r"(a2), "r"(a3), "r"(b0), "r"(b1));
}
__device__ __forceinline__ void red_v4(float* p, float a, float b, float c, float d) {
    asm volatile("red.global.add.v4.f32 [%0], {%1, %2, %3, %4};"
                 :: "l"(p), "f"(a), "f"(b), "f"(c), "f"(d) : "memory");
}
__device__ __forceinline__ void red_f32(float* p, float a) {
    asm volatile("red.global.add.f32 [%0], %1;" :: "l"(p), "f"(a) : "memory");
}
// 256-bit loads/stores with L2 priority hints (the only width ptxas accepts hints on)
__device__ __forceinline__ void ldg_el8(const float* p, float v[8]) {
    uint32_t r0,r1,r2,r3,r4,r5,r6,r7;
    asm volatile("ld.global.nc.L2::evict_last.v8.b32 {%0,%1,%2,%3,%4,%5,%6,%7}, [%8];"
                 : "=r"(r0),"=r"(r1),"=r"(r2),"=r"(r3),"=r"(r4),"=r"(r5),"=r"(r6),"=r"(r7)
                 : "l"(p));
    v[0]=__uint_as_float(r0); v[1]=__uint_as_float(r1);
    v[2]=__uint_as_float(r2); v[3]=__uint_as_float(r3);
    v[4]=__uint_as_float(r4); v[5]=__uint_as_float(r5);
    v[6]=__uint_as_float(r6); v[7]=__uint_as_float(r7);
}
__device__ __forceinline__ void ldg_ef8(const float* p, float v[8]) {
    uint32_t r0,r1,r2,r3,r4,r5,r6,r7;
    asm volatile("ld.global.L2::evict_first.v8.b32 {%0,%1,%2,%3,%4,%5,%6,%7}, [%8];"
                 : "=r"(r0),"=r"(r1),"=r"(r2),"=r"(r3),"=r"(r4),"=r"(r5),"=r"(r6),"=r"(r7)
                 : "l"(p));
    v[0]=__uint_as_float(r0); v[1]=__uint_as_float(r1);
    v[2]=__uint_as_float(r2); v[3]=__uint_as_float(r3);
    v[4]=__uint_as_float(r4); v[5]=__uint_as_float(r5);
    v[6]=__uint_as_float(r6); v[7]=__uint_as_float(r7);
}
__device__ __forceinline__ void stg_ef8(float* p, const float v[8]) {
    asm volatile("st.global.L2::evict_first.v8.b32 [%0], {%1,%2,%3,%4,%5,%6,%7,%8};"
                 :: "l"(p),
                    "r"(__float_as_uint(v[0])), "r"(__float_as_uint(v[1])),
                    "r"(__float_as_uint(v[2])), "r"(__float_as_uint(v[3])),
                    "r"(__float_as_uint(v[4])), "r"(__float_as_uint(v[5])),
                    "r"(__float_as_uint(v[6])), "r"(__float_as_uint(v[7]))
                 : "memory");
}

// ---- smem layout: padded 272B rows (16B pad -> ldmatrix conflict-free) ----
#define SK    272
#define S_AH  0
#define S_AL  34816
#define S_WH  69632
#define S_WL  104448
#define S_TOT 139264

#define GT 512   // 16 warps/CTA -> 4 warps per SMSP

__device__ __forceinline__ void split_bf16(float x, __nv_bfloat16& h, __nv_bfloat16& l) {
    h = __float2bfloat16(x);
    l = __float2bfloat16(x - __bfloat162float(h));
}

__device__ __forceinline__ void conv_W(const float* __restrict__ W, char* smem, int tid) {
    for (int i = tid; i < 4096; i += GT) {
        int k = i >> 5, n4 = (i & 31) << 2;
        float4 w = *reinterpret_cast<const float4*>(W + k * 128 + n4);
        const float* wp = &w.x;
        #pragma unroll
        for (int j = 0; j < 4; j++) {
            __nv_bfloat16 h, l;
            split_bf16(wp[j], h, l);
            int off = (n4 + j) * SK + k * 2;
            *reinterpret_cast<__nv_bfloat16*>(smem + S_WH + off) = h;
            *reinterpret_cast<__nv_bfloat16*>(smem + S_WL + off) = l;
        }
    }
}

__device__ __forceinline__ void stage_A(const float* __restrict__ A, long rows, long t,
                                        float4* rg, int tid) {
    #pragma unroll
    for (int i = 0; i < 8; i++) {
        int idx = i * GT + tid;
        int m = idx >> 5, c4 = (idx & 31) << 2;
        long row = t * 128 + m;
        rg[i] = (row < rows) ? *reinterpret_cast<const float4*>(A + row * 128 + c4)
                             : make_float4(0.f, 0.f, 0.f, 0.f);
    }
}

__device__ __forceinline__ void store_A(const float4* rg, char* smem, int tid) {
    #pragma unroll
    for (int i = 0; i < 8; i++) {
        int idx = i * GT + tid;
        int m = idx >> 5, c4 = (idx & 31) << 2;
        const float* ap = &rg[i].x;
        __nv_bfloat16 h0, l0, h1, l1, h2, l2, h3, l3;
        split_bf16(ap[0], h0, l0); split_bf16(ap[1], h1, l1);
        split_bf16(ap[2], h2, l2); split_bf16(ap[3], h3, l3);
        __nv_bfloat162 hp0 = __halves2bfloat162(h0, h1), hp1 = __halves2bfloat162(h2, h3);
        __nv_bfloat162 lp0 = __halves2bfloat162(l0, l1), lp1 = __halves2bfloat162(l2, l3);
        int off = m * SK + c4 * 2;
        *reinterpret_cast<uint2*>(smem + S_AH + off) =
            make_uint2(*reinterpret_cast<uint32_t*>(&hp0), *reinterpret_cast<uint32_t*>(&hp1));
        *reinterpret_cast<uint2*>(smem + S_AL + off) =
            make_uint2(*reinterpret_cast<uint32_t*>(&lp0), *reinterpret_cast<uint32_t*>(&lp1));
    }
}

// ================ GEMM: C[rows x 128] = A @ W + bias ================
// 16 warps: warp grid 4M x 4N, warp tile M32 x N32.
// acc layout: [nb*16 + mb*8 + n8*4 + {0..3}], nb = n16 block 0..1, mb = m16 block 0..1.
__global__ void __launch_bounds__(GT, 1)
hmma_gemm_kernel(const float* __restrict__ A, const float* __restrict__ W,
                 const float* __restrict__ bias, float* __restrict__ C,
                 long rows, long ntiles) {
    extern __shared__ __align__(16) char smem[];
    const uint32_t sb = smem_u32(smem);
    const int tid = threadIdx.x, wid = tid >> 5, lane = tid & 31;
    const int mw = wid & 3, nw = wid >> 2;

    conv_W(W, smem, tid);

    const int q = lane >> 3, r = lane & 7;
    const uint32_t aRow = (uint32_t)(mw * 32 + r + (q & 1) * 8);
    const uint32_t a_kb = (uint32_t)((q >> 1) * 16);
    const uint32_t aH0 = sb + S_AH + aRow * SK + a_kb;
    const uint32_t aH1 = aH0 + 16 * SK;
    const uint32_t aL0 = sb + S_AL + aRow * SK + a_kb;
    const uint32_t aL1 = aL0 + 16 * SK;
    const uint32_t bRow = (uint32_t)(nw * 32 + r + (q >> 1) * 8);
    const uint32_t b_kb = (uint32_t)((q & 1) * 16);
    const uint32_t bHb = sb + S_WH + bRow * SK + b_kb;
    const uint32_t bLb = sb + S_WL + bRow * SK + b_kb;

    float4 rg[8];
    long t = blockIdx.x;
    stage_A(A, rows, t, rg, tid);
    __syncthreads();

    for (; t < ntiles; ) {
        store_A(rg, smem, tid);
        __syncthreads();

        long tn = t + gridDim.x;
        if (tn < ntiles) stage_A(A, rows, tn, rg, tid);

        float acc[32];
        #pragma unroll
        for (int i = 0; i < 32; i++) acc[i] = 0.f;

        #pragma unroll
        for (int ks = 0; ks < 8; ks++) {
            const uint32_t ko = ks * 32;
            uint32_t h00, h01, h02, h03, h10, h11, h12, h13;
            uint32_t l00, l01, l02, l03, l10, l11, l12, l13;
            ldsm4(h00, h01, h02, h03, aH0 + ko);
            ldsm4(h10, h11, h12, h13, aH1 + ko);
            ldsm4(l00, l01, l02, l03, aL0 + ko);
            ldsm4(l10, l11, l12, l13, aL1 + ko);
            #pragma unroll
            for (int nb = 0; nb < 2; nb++) {
                const uint32_t off = (uint32_t)nb * (16 * SK) + ko;
                uint32_t xh0, xh1, xh2, xh3, xl0, xl1, xl2, xl3;
                ldsm4(xh0, xh1, xh2, xh3, bHb + off);
                ldsm4(xl0, xl1, xl2, xl3, bLb + off);
                float* c00 = acc + nb * 16;
                float* c01 = acc + nb * 16 + 4;
                float* c10 = acc + nb * 16 + 8;
                float* c11 = acc + nb * 16 + 12;
                // hi*hi
                mma16816(c00, h00, h01, h02, h03, xh0, xh1);
                mma16816(c01, h00, h01, h02, h03, xh2, xh3);
                mma16816(c10, h10, h11, h12, h13, xh0, xh1);
                mma16816(c11, h10, h11, h12, h13, xh2, xh3);
                // hi*lo
                mma16816(c00, h00, h01, h02, h03, xl0, xl1);
                mma16816(c01, h00, h01, h02, h03, xl2, xl3);
                mma16816(c10, h10, h11, h12, h13, xl0, xl1);
                mma16816(c11, h10, h11, h12, h13, xl2, xl3);
                // lo*hi
                mma16816(c00, l00, l01, l02, l03, xh0, xh1);
                mma16816(c01, l00, l01, l02, l03, xh2, xh3);
                mma16816(c10, l10, l11, l12, l13, xh0, xh1);
                mma16816(c11, l10, l11, l12, l13, xh2, xh3);
            }
        }

        // epilogue: add bias, store C
        const long mbase = t * 128 + mw * 32;
        #pragma unroll
        for (int nb = 0; nb < 2; nb++) {
            #pragma unroll
            for (int n8 = 0; n8 < 2; n8++) {
                int col = nw * 32 + nb * 16 + n8 * 8 + (lane & 3) * 2;
                float2 bb = *reinterpret_cast<const float2*>(bias + col);
                #pragma unroll
                for (int mb = 0; mb < 2; mb++) {
                    const float* cp = acc + nb * 16 + mb * 8 + n8 * 4;
                    long r0 = mbase + mb * 16 + (lane >> 2);
                    long r1 = r0 + 8;
                    if (r0 < rows)
                        *reinterpret_cast<float2*>(C + r0 * 128 + col) =
                            make_float2(cp[0] + bb.x, cp[1] + bb.y);
                    if (r1 < rows)
                        *reinterpret_cast<float2*>(C + r1 * 128 + col) =
                            make_float2(cp[2] + bb.x, cp[3] + bb.y);
                }
            }
        }
        __syncthreads();
        t = tn;
    }
}

// ================= non-GEMM kernels =================
__global__ void zero_kernel(int N) {
    int i = blockIdx.x * blockDim.x + threadIdx.x;
    if (i < N * 128) g_wV[i] = 0.f;
    if (i < N * 8)   g_z[i]  = 0.f;
}

// 2 edges per warp: lanes 0-15 -> edge 0, lanes 16-31 -> edge 1; 8 floats per lane.
__global__ void __launch_bounds__(256)
edge_epilogue_kernel(const float* __restrict__ envelope,
                     const int* __restrict__ src, const int* __restrict__ dst,
                     float* __restrict__ eout, long E) {
    long gw = (long)blockIdx.x * 8 + (threadIdx.x >> 5);
    int lane = threadIdx.x & 31;
    long ed = gw * 2 + (lane >> 4);
    if (ed >= E) return;

    int si = __ldg(src + ed);
    int di = __ldg(dst + ed);
    float env = __ldg(envelope + ed);

    int c = (lane & 15) * 8;
    float kv[8], qv[8], vv[8], pv[8];
    ldg_el8(g_K + (long)si * 128 + c, kv);
    ldg_el8(g_Q + (long)di * 128 + c, qv);
    ldg_el8(g_V + (long)si * 128 + c, vv);
    float* ep = eout + ed * 128 + c;
    ldg_ef8(ep, pv);

    float sc[8];
    float part = 0.f;
    #pragma unroll
    for (int i = 0; i < 8; i++) {
        sc[i] = kv[i] * qv[i] * 0.25f * pv[i];
        part += sc[i];
    }
    // head = (lane&15)>>1; pair lanes (2h, 2h+1) cover one 16-float head
    part += __shfl_xor_sync(0xFFFFFFFFu, part, 1);
    float s = __expf(fminf(fmaxf(part, -5.f), 5.f));
    float es = env * s;

    stg_ef8(ep, sc);

    float* w = g_wV + (long)di * 128 + c;
    red_v4(w,     vv[0] * es, vv[1] * es, vv[2] * es, vv[3] * es);
    red_v4(w + 4, vv[4] * es, vv[5] * es, vv[6] * es, vv[7] * es);
    if ((lane & 1) == 0) red_f32(g_z + (long)di * 8 + ((lane & 15) >> 1), s);
}

__global__ void norm_kernel(float* __restrict__ vout, int N) {
    int i = blockIdx.x * blockDim.x + threadIdx.x;
    if (i < N * 128) {
        int n = i >> 7;
        int c = i & 127;
        vout[i] = g_wV[i] / (g_z[n * 8 + (c >> 4)] + 1e-6f);
    }
}

extern "C" void kernel_launch(void* const* d_in, const int* in_sizes, int n_in,
                              void* d_out, int out_size) {
    const float* v        = (const float*)d_in[0];
    const float* e        = (const float*)d_in[1];
    const float* envelope = (const float*)d_in[2];
    const float* Wq       = (const float*)d_in[3];
    const float* bq       = (const float*)d_in[4];
    const float* Wk       = (const float*)d_in[5];
    const float* bk       = (const float*)d_in[6];
    const float* Wv       = (const float*)d_in[7];
    const float* bv       = (const float*)d_in[8];
    const float* We       = (const float*)d_in[9];
    const float* be       = (const float*)d_in[10];
    const int*   src      = (const int*)d_in[11];
    const int*   dst      = (const int*)d_in[12];

    int N = in_sizes[0] / 128;
    long E = in_sizes[11];

    float* out  = (float*)d_out;
    float* vout = out;
    float* eout = out + (long)N * 128;

    float *gq, *gk, *gv;
    cudaGetSymbolAddress((void**)&gq, g_Q);
    cudaGetSymbolAddress((void**)&gk, g_K);
    cudaGetSymbolAddress((void**)&gv, g_V);
    cudaFuncSetAttribute(hmma_gemm_kernel, cudaFuncAttributeMaxDynamicSharedMemorySize, S_TOT);

    long tilesN = (N + 127) / 128;
    long tilesE = (E + 127) / 128;
    int gridN = (int)((tilesN < 148) ? tilesN : 148);
    int gridE = (int)((tilesE < 148) ? tilesE : 148);

    zero_kernel<<<(N * 128 + 255) / 256, 256>>>(N);
    hmma_gemm_kernel<<<gridN, GT, S_TOT>>>(v, Wq, bq, gq, N, tilesN);
    hmma_gemm_kernel<<<gridN, GT, S_TOT>>>(v, Wk, bk, gk, N, tilesN);
    hmma_gemm_kernel<<<gridN, GT, S_TOT>>>(v, Wv, bv, gv, N, tilesN);
    hmma_gemm_kernel<<<gridE, GT, S_TOT>>>(e, We, be, eout, E, tilesE);
    edge_epilogue_kernel<<<(int)((E + 15) / 16), 256>>>(envelope, src, dst, eout, E);
    norm_kernel<<<(N * 128 + 255) / 256, 256>>>(vout, N);
}